// round 16
// baseline (speedup 1.0000x reference)
#include <cuda_runtime.h>
#include <math_constants.h>

// Fixed shapes per reference setup_inputs
#define BATCH   8
#define NPTS    8192
#define NQ      (2 * BATCH * NPTS)     // 131072
#define EPSF    1e-12f
#define SCALE   (1.0f / 131072.0f)

// Grid parameters (cell hash: x fastest, z slowest)
#define G       32
#define NCELLS  (G * G * G)            // 32768
#define GLO     (-4.0f)
#define H       0.25f
#define INVH    4.0f
#define NCLOUD  16
#define BIGM    1e9f

#define NBLK    1024
#define NTHR    128
#define PAIRS   8
#define PBLK    (NBLK / PAIRS)         // 128 blocks per batch-pair

// Row stride NCELLS+4 keeps every row 16B-aligned for int4 access.
#define CSTRIDE (NCELLS + 4)

// Scratch (no cudaMalloc allowed). Zero-init at load. g_hist re-zeroed in
// phase D, g_psum/g_done by the last finishing block, g_barc staggered.
__device__ float4 g_pts[NCLOUD][NPTS];
__device__ int    g_hist[NCLOUD][NCELLS];
__device__ int    g_cellstart[NCLOUD][CSTRIDE];
__device__ int    g_btot[PAIRS][PBLK];
__device__ int    g_barc[PAIRS][4];
__device__ float  g_psum[PAIRS];
__device__ int    g_done;

__device__ __forceinline__ int cell_coord(float v) {
    int c = (int)((v - GLO) * INVH);
    return min(max(c, 0), G - 1);
}

// Pair-scoped grid barrier (128 blocks). All 1024 blocks co-resident
// (__launch_bounds__(128,8) -> 8 blocks/SM), so no deadlock.
__device__ __forceinline__ void pair_barrier(int pair, int id) {
    __syncthreads();
    if (threadIdx.x == 0) {
        __threadfence();
        atomicAdd(&g_barc[pair][id], 1);
        while (atomicAdd(&g_barc[pair][id], 0) < PBLK) { }
    }
    __syncthreads();
}

// Dual-accumulator candidate scan (two independent fminf chains).
__device__ __forceinline__ void scan_pts(const float4* __restrict__ P,
                                         int j0, int j1,
                                         float ax, float ay, float az,
                                         float& lbA, float& lbB) {
    int j = j0;
    for (; j + 1 < j1; j += 2) {
        float4 p = P[j];
        float4 r = P[j + 1];
        float tA = fmaf(az, p.z, p.w);
        float tB = fmaf(az, r.z, r.w);
        tA = fmaf(ay, p.y, tA);
        tB = fmaf(ay, r.y, tB);
        tA = fmaf(ax, p.x, tA);
        tB = fmaf(ax, r.x, tB);
        lbA = fminf(lbA, tA);
        lbB = fminf(lbB, tB);
    }
    if (j < j1) {
        float4 p = P[j];
        float t = fmaf(az, p.z, p.w);
        t = fmaf(ay, p.y, t);
        t = fmaf(ax, p.x, t);
        lbA = fminf(lbA, t);
    }
}

// Exact margin from q-coord to the scanned box faces along one axis.
// Clamped domain faces -> nothing unscanned beyond them -> infinite margin.
__device__ __forceinline__ float axis_margin(float qv, int lo, int hi) {
    float ml = (lo > 0)     ? (qv - (GLO + (float)lo * H))       : BIGM;
    float mh = (hi < G - 1) ? ((GLO + (float)(hi + 1) * H) - qv) : BIGM;
    return fminf(ml, mh);
}

__device__ __forceinline__ int warp_min(int v) {
#pragma unroll
    for (int o = 16; o > 0; o >>= 1)
        v = min(v, __shfl_xor_sync(0xFFFFFFFFu, v, o));
    return v;
}
__device__ __forceinline__ int warp_max(int v) {
#pragma unroll
    for (int o = 16; o > 0; o >>= 1)
        v = max(v, __shfl_xor_sync(0xFFFFFFFFu, v, o));
    return v;
}

__global__ void __launch_bounds__(NTHR, 8)
fused_kernel(const float* __restrict__ xyz1,
             const float* __restrict__ xyz2,
             float* __restrict__ out) {
    __shared__ int   s_i[32];
    __shared__ float s_f[4];

    const int tix  = threadIdx.x;
    const int lane = tix & 31;
    const int warp = tix >> 5;
    const int b    = blockIdx.x;
    const int pair = b >> 7;               // batch index, 8 pairs
    const int pb   = b & (PBLK - 1);       // block within pair
    const int lp   = pb * NTHR + tix;      // 0..16383 within pair

    // ================= A: histogram + rank =================
    if (pb == 0 && tix == 0) g_barc[pair][3] = 0;

    int   srcp = lp >> 13;                 // 0 or 1 (which input)
    int   i0   = lp & (NPTS - 1);
    const float* pp = ((srcp == 0) ? xyz1 : xyz2)
                    + (size_t)(pair * NPTS + i0) * 3;
    float px = pp[0], py = pp[1], pz = pp[2];     // live until phase C
    int   pcloud = (srcp << 3) + pair;
    int   pcell  = (cell_coord(pz) * G + cell_coord(py)) * G + cell_coord(px);
    int   prank  = atomicAdd(&g_hist[pcloud][pcell], 1);  // rank within cell

    pair_barrier(pair, 0);

    // ================= B1: block-local sums over 512 cells =================
    const int grp     = pb >> 6;                      // 0: cloud pair, 1: pair+8
    const int cloud_b = (grp << 3) + pair;
    const int cbase   = ((pb & 63) << 9) + (tix << 2);  // 4 cells per thread
    int4 h = *(const int4*)&g_hist[cloud_b][cbase];
    int hs = h.x + h.y + h.z + h.w;

    int incl = hs;                                    // warp inclusive scan
#pragma unroll
    for (int o = 1; o < 32; o <<= 1) {
        int u = __shfl_up_sync(0xFFFFFFFFu, incl, o);
        if (lane >= o) incl += u;
    }
    if (lane == 31) s_i[warp] = incl;
    __syncthreads();
    int woff = 0;
#pragma unroll
    for (int w = 0; w < 4; w++) if (w < warp) woff += s_i[w];
    int ebase = woff + incl - hs;                     // block-exclusive base
    if (tix == 0) g_btot[pair][pb] = s_i[0] + s_i[1] + s_i[2] + s_i[3];

    pair_barrier(pair, 1);

    // ================= B2: cross-block offsets, write cellstart =====
    if (pb == 0 && tix == 0) g_barc[pair][0] = 0;
    {
        int nb = pb & 63;
        int v = (tix < nb) ? g_btot[pair][(grp << 6) + tix] : 0;
#pragma unroll
        for (int o = 16; o > 0; o >>= 1)
            v += __shfl_down_sync(0xFFFFFFFFu, v, o);
        __syncthreads();
        if (lane == 0) s_i[warp] = v;
        __syncthreads();
        int off  = s_i[0] + s_i[1] + s_i[2] + s_i[3];
        int base = off + ebase;
        int4 cs;
        cs.x = base;
        cs.y = cs.x + h.x;
        cs.z = cs.y + h.y;
        cs.w = cs.z + h.z;
        *(int4*)&g_cellstart[cloud_b][cbase] = cs;
        if (nb == 0 && tix == 0) g_cellstart[cloud_b][NCELLS] = NPTS;
    }

    pair_barrier(pair, 2);

    // ================= C: rank-based scatter (no atomics) =================
    if (pb == 0 && tix == 0) g_barc[pair][1] = 0;
    {
        int slot = g_cellstart[pcloud][pcell] + prank;
        g_pts[pcloud][slot] =
            make_float4(px, py, pz, px * px + py * py + pz * pz);
    }

    pair_barrier(pair, 3);

    // ================= D: query + tail + reduce =================
    if (pb == 0 && tix == 0) g_barc[pair][2] = 0;
    ((int4*)g_hist[pcloud])[i0] = make_int4(0, 0, 0, 0);  // ready next launch

    // warp remap within pair; each warp keeps 32 contiguous sorted queries.
    int wid  = lp >> 5;                             // 0..511
    int nwid = (wid & 31) * 16 + (wid >> 5);        // bijection on [0,512)
    int tid2 = nwid * 32 + lane;                    // query within pair

    int srcq    = tid2 >> 13;
    int i       = tid2 & (NPTS - 1);
    int cloud_q = (srcq << 3) + pair;
    int cand    = cloud_q ^ 8;

    float4 q = g_pts[cloud_q][i];
    float n2q = q.w;
    float ax = -2.0f * q.x, ay = -2.0f * q.y, az = -2.0f * q.z;
    int cx = cell_coord(q.x);
    int cy = cell_coord(q.y);
    int cz = cell_coord(q.z);

    const float4* __restrict__ P = g_pts[cand];
    const int*    __restrict__ S = g_cellstart[cand];

    // ---- pass 1: warp-union box (fast) or per-lane 3x3x3 (fallback) ----
    float bA = CUDART_INF_F, bB = CUDART_INF_F;
    float m1;

    int cxmin = warp_min(cx), cxmax = warp_max(cx);
    int cymin = warp_min(cy), cymax = warp_max(cy);
    int czmin = warp_min(cz), czmax = warp_max(cz);
    bool fast = (cxmax - cxmin <= 4) && (cymax - cymin <= 1)
             && (czmax - czmin <= 1);               // warp-uniform

    if (fast) {
        // Whole warp streams the union box: broadcast headers + uniform
        // loops; every lane evaluates every point (superset of its own
        // 3x3x3, so margins vs the union box remain exact).
        int bx0 = max(cxmin - 1, 0), bx1 = min(cxmax + 1, G - 1);
        int by0 = max(cymin - 1, 0), by1 = min(cymax + 1, G - 1);
        int bz0 = max(czmin - 1, 0), bz1 = min(czmax + 1, G - 1);
        for (int zc = bz0; zc <= bz1; zc++) {
            for (int yc = by0; yc <= by1; yc++) {
                int row = (zc * G + yc) * G;
                int j0 = S[row + bx0];              // broadcast (uniform addr)
                int j1 = S[row + bx1 + 1];
                scan_pts(P, j0, j1, ax, ay, az, bA, bB);
            }
        }
        m1 = axis_margin(q.x, bx0, bx1);
        m1 = fminf(m1, axis_margin(q.y, by0, by1));
        m1 = fminf(m1, axis_margin(q.z, bz0, bz1));
    } else {
        // per-lane 3x3x3 with hoisted headers (18 independent LDGs)
        int x0 = max(cx - 1, 0);
        int x1 = min(cx + 1, G - 1);
        int j0a[9], j1a[9];
#pragma unroll
        for (int k = 0; k < 9; k++) {
            int dz = k / 3 - 1;
            int dy = k - (k / 3) * 3 - 1;
            int zc = cz + dz, yc = cy + dy;
            bool ok = ((unsigned)zc < G) && ((unsigned)yc < G);
            int row = (zc * G + yc) * G;
            j0a[k] = ok ? S[row + x0] : 0;
            j1a[k] = ok ? S[row + x1 + 1] : 0;
        }
#pragma unroll
        for (int k = 0; k < 9; k++)
            scan_pts(P, j0a[k], j1a[k], ax, ay, az, bA, bB);
        m1 = axis_margin(q.x, x0, x1);
        m1 = fminf(m1, axis_margin(q.y, max(cy - 1, 0), min(cy + 1, G - 1)));
        m1 = fminf(m1, axis_margin(q.z, max(cz - 1, 0), min(cz + 1, G - 1)));
    }
    float best = fminf(bA, bB);

    float d2 = n2q + best;
    float contrib = 0.0f;
    bool done = (d2 <= m1 * m1);
    if (done) contrib = sqrtf(fmaxf(d2, EPSF));

    // pass 2 (per-thread, parallel across needy lanes): r=2 shell only
    int xb0 = max(cx - 2, 0), xb1 = min(cx + 2, G - 1);
    if (!done) {
#pragma unroll 5
        for (int k = 0; k < 25; k++) {
            int dz = k / 5 - 2;
            int dy = k - (k / 5) * 5 - 2;
            int zc = cz + dz, yc = cy + dy;
            if ((unsigned)zc >= G || (unsigned)yc >= G) continue;
            int row = (zc * G + yc) * G;
            if (abs(dz) == 2 || abs(dy) == 2) {
                scan_pts(P, S[row + xb0], S[row + xb1 + 1], ax, ay, az, bA, bB);
            } else {
                int xm = cx - 2;
                if (xm >= 0) scan_pts(P, S[row + xm], S[row + xm + 1],
                                      ax, ay, az, bA, bB);
                int xp = cx + 2;
                if (xp < G)  scan_pts(P, S[row + xp], S[row + xp + 1],
                                      ax, ay, az, bA, bB);
            }
        }
        best = fminf(bA, bB);

        float m2 = axis_margin(q.x, xb0, xb1);
        m2 = fminf(m2, axis_margin(q.y, max(cy - 2, 0), min(cy + 2, G - 1)));
        m2 = fminf(m2, axis_margin(q.z, max(cz - 2, 0), min(cz + 2, G - 1)));

        d2 = n2q + best;
        done = (d2 <= m2 * m2);
        if (done) contrib = sqrtf(fmaxf(d2, EPSF));
    }

    // residual: warp-cooperative z-slab doubling (z slowest sort dim).
    unsigned needy = __ballot_sync(0xFFFFFFFFu, !done);
    while (needy) {
        int l = __ffs(needy) - 1;
        needy &= needy - 1;
        float bax = __shfl_sync(0xFFFFFFFFu, ax, l);
        float bay = __shfl_sync(0xFFFFFFFFu, ay, l);
        float baz = __shfl_sync(0xFFFFFFFFu, az, l);
        float bqz = __shfl_sync(0xFFFFFFFFu, q.z, l);
        float bn2 = __shfl_sync(0xFFFFFFFFu, n2q, l);
        float bb  = __shfl_sync(0xFFFFFFFFu, best, l);
        int   bcz = __shfl_sync(0xFFFFFFFFu, cz, l);

        int k = 4;
        while (true) {
            int z0 = max(bcz - k, 0);
            int z1 = min(bcz + k, G - 1);
            int j0 = S[z0 * (G * G)];
            int j1 = S[(z1 + 1) * (G * G)];
            float lb = CUDART_INF_F;
            for (int j = j0 + lane; j < j1; j += 32) {
                float4 p = P[j];
                float t = fmaf(baz, p.z, p.w);
                t = fmaf(bay, p.y, t);
                t = fmaf(bax, p.x, t);
                lb = fminf(lb, t);
            }
#pragma unroll
            for (int o = 16; o > 0; o >>= 1)
                lb = fminf(lb, __shfl_xor_sync(0xFFFFFFFFu, lb, o));
            bb = fminf(bb, lb);
            float mz = axis_margin(bqz, z0, z1);
            if ((z0 == 0 && z1 == G - 1) || bn2 + bb <= mz * mz) break;
            k *= 2;
        }
        if (lane == l) contrib = sqrtf(fmaxf(bn2 + bb, EPSF));
    }

    // block reduce -> pair partial; last block overall writes out.
#pragma unroll
    for (int o = 16; o > 0; o >>= 1)
        contrib += __shfl_down_sync(0xFFFFFFFFu, contrib, o);
    if (lane == 0) s_f[warp] = contrib;
    __syncthreads();
    if (tix == 0) {
        atomicAdd(&g_psum[pair], s_f[0] + s_f[1] + s_f[2] + s_f[3]);
        __threadfence();                       // psum visible before done++
        int d = atomicAdd(&g_done, 1);
        if (d == NBLK - 1) {                   // last block: finalize + reset
            float t = 0.0f;
#pragma unroll
            for (int p = 0; p < PAIRS; p++) { t += g_psum[p]; g_psum[p] = 0.0f; }
            out[0] = t * SCALE;
            g_done = 0;
        }
    }
}

extern "C" void kernel_launch(void* const* d_in, const int* in_sizes, int n_in,
                              void* d_out, int out_size) {
    const float* xyz1 = (const float*)d_in[0];
    const float* xyz2 = (const float*)d_in[1];
    float* out = (float*)d_out;

    fused_kernel<<<NBLK, NTHR>>>(xyz1, xyz2, out);
}

// round 17
// speedup vs baseline: 1.5397x; 1.5397x over previous
#include <cuda_runtime.h>
#include <math_constants.h>

// Fixed shapes per reference setup_inputs
#define BATCH   8
#define NPTS    8192
#define NQ      (2 * BATCH * NPTS)     // 131072
#define EPSF    1e-12f
#define SCALE   (1.0f / 131072.0f)

// Grid parameters (cell hash: x fastest, z slowest)
#define G       32
#define NCELLS  (G * G * G)            // 32768
#define GLO     (-4.0f)
#define H       0.25f
#define INVH    4.0f
#define NCLOUD  16
#define BIGM    1e9f

#define NBLK    128
#define NTHR    1024
#define SMEMB   (NPTS * 16)            // 128KB candidate cloud

// Row stride NCELLS+4 keeps every row 16B-aligned for int4 access.
#define CSTRIDE (NCELLS + 4)

// Scratch (no cudaMalloc allowed). Zero-init at load. g_hist re-zeroed in
// phase D; g_barc staggered-reset across launches.
__device__ float4 g_pts[NCLOUD][NPTS];
__device__ int    g_hist[NCLOUD][NCELLS];
__device__ int    g_cellstart[NCLOUD][CSTRIDE];
__device__ int    g_btot[NBLK];
__device__ int    g_barc[4];

__device__ __forceinline__ int cell_coord(float v) {
    int c = (int)((v - GLO) * INVH);
    return min(max(c, 0), G - 1);
}

// Global grid barrier over 128 blocks. All resident: 1 block/SM (128KB smem),
// 128 <= 148 SMs, regs capped by __launch_bounds__(1024).
__device__ __forceinline__ void grid_barrier(int id) {
    __syncthreads();
    if (threadIdx.x == 0) {
        __threadfence();
        atomicAdd(&g_barc[id], 1);
        while (atomicAdd(&g_barc[id], 0) < NBLK) { }
    }
    __syncthreads();
}

// Dual-accumulator candidate scan over the SMEM-staged cloud.
__device__ __forceinline__ void scan_sh(const float4* __restrict__ P,
                                        int j0, int j1,
                                        float ax, float ay, float az,
                                        float& lbA, float& lbB) {
    int j = j0;
    for (; j + 1 < j1; j += 2) {
        float4 p = P[j];
        float4 r = P[j + 1];
        float tA = fmaf(az, p.z, p.w);
        float tB = fmaf(az, r.z, r.w);
        tA = fmaf(ay, p.y, tA);
        tB = fmaf(ay, r.y, tB);
        tA = fmaf(ax, p.x, tA);
        tB = fmaf(ax, r.x, tB);
        lbA = fminf(lbA, tA);
        lbB = fminf(lbB, tB);
    }
    if (j < j1) {
        float4 p = P[j];
        float t = fmaf(az, p.z, p.w);
        t = fmaf(ay, p.y, t);
        t = fmaf(ax, p.x, t);
        lbA = fminf(lbA, t);
    }
}

// Exact margin from q-coord to scanned box faces along one axis.
// Clamped domain faces -> nothing unscanned beyond -> infinite margin.
__device__ __forceinline__ float axis_margin(float qv, int lo, int hi) {
    float ml = (lo > 0)     ? (qv - (GLO + (float)lo * H))       : BIGM;
    float mh = (hi < G - 1) ? ((GLO + (float)(hi + 1) * H) - qv) : BIGM;
    return fminf(ml, mh);
}

extern __shared__ float4 sh_pts[];      // [NPTS] candidate cloud

__global__ void __launch_bounds__(NTHR, 1)
fused_kernel(const float* __restrict__ xyz1,
             const float* __restrict__ xyz2,
             float* __restrict__ out) {
    __shared__ int   s_i[32];
    __shared__ float s_f[32];

    const int tix  = threadIdx.x;
    const int lane = tix & 31;
    const int warp = tix >> 5;          // 0..31
    const int b    = blockIdx.x;        // 0..127
    const int lin  = b * NTHR + tix;    // 0..131071

    // ================= A: histogram + rank =================
    // barc[3] left set by PREVIOUS launch; all blocks reach barrier 3 only
    // after barrier 0, which needs block 0's arrival, after this reset.
    if (lin == 0) { out[0] = 0.0f; g_barc[3] = 0; }

    int   src    = lin >> 16;           // 0 or 1
    int   within = lin & 0xFFFF;
    const float* pp = ((src == 0) ? xyz1 : xyz2) + (size_t)within * 3;
    float px = pp[0], py = pp[1], pz = pp[2];        // live until phase C
    int   pcloud = (src << 3) + (within >> 13);
    int   i0     = within & (NPTS - 1);
    int   pcell  = (cell_coord(pz) * G + cell_coord(py)) * G + cell_coord(px);
    int   prank  = atomicAdd(&g_hist[pcloud][pcell], 1);

    grid_barrier(0);

    // ================= B1: block-local sums (4096 cells/block) ==============
    const int cloud_b = b >> 3;                        // 8 blocks per cloud
    const int cbase   = ((b & 7) << 12) + (tix << 2);  // 4 cells per thread
    int4 h = *(const int4*)&g_hist[cloud_b][cbase];
    int hs = h.x + h.y + h.z + h.w;

    int incl = hs;                                     // warp inclusive scan
#pragma unroll
    for (int o = 1; o < 32; o <<= 1) {
        int u = __shfl_up_sync(0xFFFFFFFFu, incl, o);
        if (lane >= o) incl += u;
    }
    if (lane == 31) s_i[warp] = incl;
    __syncthreads();
    if (warp == 0) {
        int w = s_i[lane];
#pragma unroll
        for (int o = 1; o < 32; o <<= 1) {
            int u = __shfl_up_sync(0xFFFFFFFFu, w, o);
            if (lane >= o) w += u;
        }
        s_i[lane] = w;
    }
    __syncthreads();
    int ebase = ((warp > 0) ? s_i[warp - 1] : 0) + incl - hs;
    if (tix == 0) g_btot[b] = s_i[31];

    grid_barrier(1);

    // ================= B2: cross-block offsets, write cellstart =============
    if (lin == 0) g_barc[0] = 0;         // all blocks passed barrier 0's spin
    {
        int nb = b & 7;
        int off = 0;
        for (int t = 0; t < nb; t++) off += g_btot[(cloud_b << 3) + t];
        int base = off + ebase;
        int4 cs;
        cs.x = base;
        cs.y = cs.x + h.x;
        cs.z = cs.y + h.y;
        cs.w = cs.z + h.z;
        *(int4*)&g_cellstart[cloud_b][cbase] = cs;
        if (nb == 0 && tix == 0) g_cellstart[cloud_b][NCELLS] = NPTS;
    }

    grid_barrier(2);

    // ================= C: rank-based scatter (no atomics) ==================
    if (lin == 0) g_barc[1] = 0;
    {
        int slot = g_cellstart[pcloud][pcell] + prank;
        g_pts[pcloud][slot] =
            make_float4(px, py, pz, px * px + py * py + pz * pz);
    }

    grid_barrier(3);

    // ================= D: stage candidate cloud in SMEM, query, reduce =====
    if (lin == 0) g_barc[2] = 0;
    ((int4*)g_hist[pcloud])[i0] = make_int4(0, 0, 0, 0);  // ready next launch

    const int slice = b >> 3;            // (dir<<3)+pair = query cloud
    const int kblk  = b & 7;             // block within slice
    const int cloud_q = slice;
    const int cand    = slice ^ 8;

    // bulk-stage candidate cloud: 8192 float4, coalesced, 8 per thread
#pragma unroll
    for (int j = tix; j < NPTS; j += NTHR)
        sh_pts[j] = g_pts[cand][j];
    __syncthreads();

    // interleaved chunk assignment: warp w of block k -> sorted chunk w*8+k
    // (keeps each warp's 32 queries contiguous; balances blocks)
    int chunk = warp * 8 + kblk;         // 0..255
    int i     = chunk * 32 + lane;       // query index in sorted order

    float4 q = g_pts[cloud_q][i];
    float n2q = q.w;
    float ax = -2.0f * q.x, ay = -2.0f * q.y, az = -2.0f * q.z;
    int cx = cell_coord(q.x);
    int cy = cell_coord(q.y);
    int cz = cell_coord(q.z);

    const int* __restrict__ S = g_cellstart[cand];

    // pass 1: 3x3x3, hoisted headers (18 independent LDGs), points from SMEM
    int x0 = max(cx - 1, 0);
    int x1 = min(cx + 1, G - 1);
    int j0a[9], j1a[9];
#pragma unroll
    for (int k = 0; k < 9; k++) {
        int dz = k / 3 - 1;
        int dy = k - (k / 3) * 3 - 1;
        int zc = cz + dz, yc = cy + dy;
        bool ok = ((unsigned)zc < G) && ((unsigned)yc < G);
        int row = (zc * G + yc) * G;
        j0a[k] = ok ? S[row + x0] : 0;
        j1a[k] = ok ? S[row + x1 + 1] : 0;
    }
    float bA = CUDART_INF_F, bB = CUDART_INF_F;
#pragma unroll
    for (int k = 0; k < 9; k++)
        scan_sh(sh_pts, j0a[k], j1a[k], ax, ay, az, bA, bB);
    float best = fminf(bA, bB);

    float m1 = axis_margin(q.x, x0, x1);
    m1 = fminf(m1, axis_margin(q.y, max(cy - 1, 0), min(cy + 1, G - 1)));
    m1 = fminf(m1, axis_margin(q.z, max(cz - 1, 0), min(cz + 1, G - 1)));

    float d2 = n2q + best;
    float contrib = 0.0f;
    bool done = (d2 <= m1 * m1);
    if (done) contrib = sqrtf(fmaxf(d2, EPSF));

    // pass 2 (per-thread): r=2 shell only, from SMEM
    int xb0 = max(cx - 2, 0), xb1 = min(cx + 2, G - 1);
    if (!done) {
#pragma unroll 5
        for (int k = 0; k < 25; k++) {
            int dz = k / 5 - 2;
            int dy = k - (k / 5) * 5 - 2;
            int zc = cz + dz, yc = cy + dy;
            if ((unsigned)zc >= G || (unsigned)yc >= G) continue;
            int row = (zc * G + yc) * G;
            if (abs(dz) == 2 || abs(dy) == 2) {
                scan_sh(sh_pts, S[row + xb0], S[row + xb1 + 1],
                        ax, ay, az, bA, bB);
            } else {
                int xm = cx - 2;
                if (xm >= 0) scan_sh(sh_pts, S[row + xm], S[row + xm + 1],
                                     ax, ay, az, bA, bB);
                int xp = cx + 2;
                if (xp < G)  scan_sh(sh_pts, S[row + xp], S[row + xp + 1],
                                     ax, ay, az, bA, bB);
            }
        }
        best = fminf(bA, bB);

        float m2 = axis_margin(q.x, xb0, xb1);
        m2 = fminf(m2, axis_margin(q.y, max(cy - 2, 0), min(cy + 2, G - 1)));
        m2 = fminf(m2, axis_margin(q.z, max(cz - 2, 0), min(cz + 2, G - 1)));

        d2 = n2q + best;
        done = (d2 <= m2 * m2);
        if (done) contrib = sqrtf(fmaxf(d2, EPSF));
    }

    // residual: warp-cooperative z-slab doubling over SMEM cloud
    unsigned needy = __ballot_sync(0xFFFFFFFFu, !done);
    while (needy) {
        int l = __ffs(needy) - 1;
        needy &= needy - 1;
        float bax = __shfl_sync(0xFFFFFFFFu, ax, l);
        float bay = __shfl_sync(0xFFFFFFFFu, ay, l);
        float baz = __shfl_sync(0xFFFFFFFFu, az, l);
        float bqz = __shfl_sync(0xFFFFFFFFu, q.z, l);
        float bn2 = __shfl_sync(0xFFFFFFFFu, n2q, l);
        float bb  = __shfl_sync(0xFFFFFFFFu, best, l);
        int   bcz = __shfl_sync(0xFFFFFFFFu, cz, l);

        int k = 4;
        while (true) {
            int z0 = max(bcz - k, 0);
            int z1 = min(bcz + k, G - 1);
            int j0 = S[z0 * (G * G)];
            int j1 = S[(z1 + 1) * (G * G)];
            float lb = CUDART_INF_F;
            for (int j = j0 + lane; j < j1; j += 32) {
                float4 p = sh_pts[j];
                float t = fmaf(baz, p.z, p.w);
                t = fmaf(bay, p.y, t);
                t = fmaf(bax, p.x, t);
                lb = fminf(lb, t);
            }
#pragma unroll
            for (int o = 16; o > 0; o >>= 1)
                lb = fminf(lb, __shfl_xor_sync(0xFFFFFFFFu, lb, o));
            bb = fminf(bb, lb);
            float mz = axis_margin(bqz, z0, z1);
            if ((z0 == 0 && z1 == G - 1) || bn2 + bb <= mz * mz) break;
            k *= 2;
        }
        if (lane == l) contrib = sqrtf(fmaxf(bn2 + bb, EPSF));
    }

    // block reduce (32 warps) -> one atomicAdd per block
#pragma unroll
    for (int o = 16; o > 0; o >>= 1)
        contrib += __shfl_down_sync(0xFFFFFFFFu, contrib, o);
    if (lane == 0) s_f[warp] = contrib;
    __syncthreads();
    if (warp == 0) {
        float v = s_f[lane];
#pragma unroll
        for (int o = 16; o > 0; o >>= 1)
            v += __shfl_down_sync(0xFFFFFFFFu, v, o);
        if (lane == 0) atomicAdd(out, v * SCALE);
    }
}

extern "C" void kernel_launch(void* const* d_in, const int* in_sizes, int n_in,
                              void* d_out, int out_size) {
    const float* xyz1 = (const float*)d_in[0];
    const float* xyz2 = (const float*)d_in[1];
    float* out = (float*)d_out;

    cudaFuncSetAttribute(fused_kernel,
                         cudaFuncAttributeMaxDynamicSharedMemorySize, SMEMB);
    fused_kernel<<<NBLK, NTHR, SMEMB>>>(xyz1, xyz2, out);
}